// round 17
// baseline (speedup 1.0000x reference)
#include <cuda_runtime.h>
#include <cstdint>

// Problem shape (fixed by the dataset)
#define Nn 8
#define Cc 32
#define Hh 512
#define Ww 512
#define HW (Hh * Ww)          // 262144
#define OC 32

// ---------------- device scratch (allocation-free rule) ----------------------
__device__ float    g_blockmax[2048];   // per-block |x| maxima
__device__ float    g_sw;               // weight absmax
__device__ unsigned g_tile_ctr;         // dynamic tile ticket (reset in k_absmax)
// Tensor layout (R7-proven): i -> slot=i>>3 (slot=(t*8+g)*4+tg), j=i&7
//   (half=j>>2, nt=j&3); word packs ic=(tg+half*4)*4..+3 for oc=nt*8+g, tap t.
//   (only nt=0,1 i.e. oc 0..15 are consumed by the tensor path now)
__device__ uint32_t g_qw[9 * 8 * 4 * 8];   // 9216 B
// dp4a layout, oc 16..31 only: word[(oc-16)*72 + t*8 + j] packs ic j*4..+3.
__device__ uint32_t g_qw2[16 * 72];        // 4608 B

// ---------------- kernel 1: x per-block absmax (+ weight prep in block 0) ----
__global__ void k_absmax(const float4* __restrict__ x, const float* __restrict__ w,
                         int n4) {
    __shared__ float sred[8];
    float m = 0.f;
    for (int i = blockIdx.x * blockDim.x + threadIdx.x; i < n4;
         i += gridDim.x * blockDim.x) {
        float4 v = x[i];
        m = fmaxf(m, fmaxf(fmaxf(fabsf(v.x), fabsf(v.y)),
                           fmaxf(fabsf(v.z), fabsf(v.w))));
    }
    #pragma unroll
    for (int o = 16; o; o >>= 1) m = fmaxf(m, __shfl_xor_sync(~0u, m, o));
    if ((threadIdx.x & 31) == 0) sred[threadIdx.x >> 5] = m;
    __syncthreads();
    if (threadIdx.x == 0) {
        float v = sred[0];
        #pragma unroll
        for (int j = 1; j < 8; j++) v = fmaxf(v, sred[j]);
        g_blockmax[blockIdx.x] = v;
    }

    if (blockIdx.x == 0) {   // weight absmax + quantize into both layouts
        if (threadIdx.x == 0) g_tile_ctr = 0u;   // reset ticket for k_conv
        __syncthreads();
        float mw = 0.f;
        for (int i = threadIdx.x; i < 9216; i += 256) mw = fmaxf(mw, fabsf(w[i]));
        #pragma unroll
        for (int o = 16; o; o >>= 1) mw = fmaxf(mw, __shfl_xor_sync(~0u, mw, o));
        if ((threadIdx.x & 31) == 0) sred[threadIdx.x >> 5] = mw;
        __syncthreads();
        __shared__ float s_sw;
        if (threadIdx.x == 0) {
            float v = sred[0];
            #pragma unroll
            for (int j = 1; j < 8; j++) v = fmaxf(v, sred[j]);
            s_sw = v;
            g_sw = v;
        }
        __syncthreads();
        float inv = 127.f / s_sw;
        for (int i = threadIdx.x; i < 9 * 8 * 4 * 8; i += 256) {   // tensor layout
            int slot = i >> 3, j = i & 7;
            int tg = slot & 3, g = (slot >> 2) & 7, t = slot >> 5;
            int nt = j & 3, half = j >> 2;
            int oc  = nt * 8 + g;
            int ic0 = (tg + half * 4) * 4;
            uint32_t p = 0;
            #pragma unroll
            for (int b = 0; b < 4; b++) {
                int q = __float2int_rn(w[(oc * Cc + ic0 + b) * 9 + t] * inv);
                q = max(-127, min(127, q));
                p |= (uint32_t)(q & 0xFF) << (8 * b);
            }
            g_qw[i] = p;
        }
        for (int i = threadIdx.x; i < 16 * 72; i += 256) {   // dp4a layout oc16-31
            int oc = 16 + i / 72, rem = i % 72, t = rem >> 3, j = rem & 7;
            int ic0 = j * 4;
            uint32_t p = 0;
            #pragma unroll
            for (int b = 0; b < 4; b++) {
                int q = __float2int_rn(w[(oc * Cc + ic0 + b) * 9 + t] * inv);
                q = max(-127, min(127, q));
                p |= (uint32_t)(q & 0xFF) << (8 * b);
            }
            g_qw2[i] = p;
        }
    }
}

// ---------------- kernel 2: fused quantize + intra-warp dual-pipe conv ------
// Every warp: 16 px; oc 0-15 on tensor pipe (2x m16n8k32 per tap), oc 16-31
// on fma pipe (dp4a, lane = 1 px x 8 oc). Per-SMSP balance is structural.
// Ring uses a 16B XOR swizzle so 32B-stride pixel reads are conflict-free.

__device__ __forceinline__ void mma_s8(int* c,
                                       uint32_t a0, uint32_t a1, uint32_t a2, uint32_t a3,
                                       uint32_t b0, uint32_t b1) {
    asm volatile(
        "mma.sync.aligned.m16n8k32.row.col.s32.s8.s8.s32 "
        "{%0,%1,%2,%3}, {%4,%5,%6,%7}, {%8,%9}, {%0,%1,%2,%3};\n"
        : "+r"(c[0]), "+r"(c[1]), "+r"(c[2]), "+r"(c[3])
        : "r"(a0), "r"(a1), "r"(a2), "r"(a3), "r"(b0), "r"(b1));
}

#define ROWS 4
#define NTILES (Nn * (Hh / ROWS) * (Ww / 128))   // 4096
#define NCTA 444                                  // 3 CTAs/SM x 148
#define RSTRIDE 4224   // 132 px * 32 B

// Swizzled in-ring byte offset of (pixel px, 16B-half h).
__device__ __forceinline__ int ring_off(int px, int h) {
    return px * 32 + ((((px >> 2) ^ h) & 1) << 4);
}

// Prologue row fill (load+quant+store). Ring px p <-> input w = w0-1+p.
__device__ __forceinline__ void load_row_full(char* dst, const float* __restrict__ xn,
                                              int r, int w0, float inv) {
    const int tid = threadIdx.x;
    const int pxm = (tid & 127) + 1, hf = tid >> 7;
    const bool vr = ((unsigned)r < (unsigned)Hh);
    const float* p = xn + (size_t)(hf * 16) * HW + (size_t)(vr ? r : 0) * Ww
                   + (w0 + (tid & 127));
    uint32_t wd[4];
    #pragma unroll
    for (int q4 = 0; q4 < 4; q4++) {
        uint32_t pw = 0;
        #pragma unroll
        for (int b = 0; b < 4; b++) {
            float v = vr ? __ldg(p + (size_t)(q4 * 4 + b) * HW) : 0.f;
            int q = max(-127, min(127, __float2int_rn(v * inv)));
            pw |= (uint32_t)(q & 0xFF) << (8 * b);
        }
        wd[q4] = pw;
    }
    *(uint4*)(dst + ring_off(pxm, hf)) = make_uint4(wd[0], wd[1], wd[2], wd[3]);
    if (tid < 64) {   // halo px 0 / 129, one channel per thread
        int hp = (tid < 32) ? 0 : 129;
        int wh = w0 - 1 + hp;
        int ch = tid & 31;
        float v = 0.f;
        if (vr && wh >= 0 && wh < Ww)
            v = __ldg(xn + (size_t)ch * HW + (size_t)r * Ww + wh);
        int q = max(-127, min(127, __float2int_rn(v * inv)));
        *(int8_t*)(dst + ring_off(hp, ch >> 4) + (ch & 15)) = (int8_t)q;
    }
}

__global__ void __launch_bounds__(256, 3) k_conv(const float* __restrict__ x,
                                                 float* __restrict__ out,
                                                 const float* __restrict__ bias) {
    __shared__ uint32_t s_w[9 * 8 * 4 * 12];  // tensor weights (13824 B)
    __shared__ uint32_t s_w2[16 * 72];        // dp4a weights oc16-31 (4608 B)
    __shared__ char     s_a[4 * RSTRIDE];     // 16896 B ring
    __shared__ float    s_red[8];
    __shared__ float    s_bias[OC];
    __shared__ float    s_scale, s_inv;
    __shared__ unsigned s_tile;

    const int tid  = threadIdx.x;
    const int warp = tid >> 5, lane = tid & 31;
    const int g    = lane >> 2, tg = lane & 3;          // tensor roles
    const int dpx  = lane & 15, och = (lane >> 4) * 8;  // dp4a: px-in-tile, oc block

    // one-time init: final absmax, both weight sets, bias
    {
        float m = 0.f;
        for (int j = tid; j < 2048; j += 256) m = fmaxf(m, g_blockmax[j]);
        #pragma unroll
        for (int o = 16; o; o >>= 1) m = fmaxf(m, __shfl_xor_sync(~0u, m, o));
        if (lane == 0) s_red[warp] = m;
    }
    if (tid < 32) s_bias[tid] = __ldg(bias + tid);
    __syncthreads();
    if (tid == 0) {
        float v = s_red[0];
        #pragma unroll
        for (int j = 1; j < 8; j++) v = fmaxf(v, s_red[j]);
        s_scale = v * g_sw * (1.f / 16129.f);
        s_inv   = 127.f / v;
    }
    for (int i = tid; i < 9 * 8 * 4 * 8; i += 256)
        s_w[(i >> 3) * 12 + (i & 7)] = g_qw[i];
    for (int i = tid; i < 16 * 72; i += 256) s_w2[i] = g_qw2[i];
    __syncthreads();
    const float inv = s_inv, sc = s_scale;

    float bv[4];   // tensor-path bias, nt = 0,1
    #pragma unroll
    for (int nt = 0; nt < 2; nt++) {
        bv[2 * nt]     = s_bias[nt * 8 + tg * 2];
        bv[2 * nt + 1] = s_bias[nt * 8 + tg * 2 + 1];
    }
    float bd[8];   // dp4a-path bias, oc 16+och .. +7
    #pragma unroll
    for (int o = 0; o < 8; o++) bd[o] = s_bias[16 + och + o];

    const int pxm = (tid & 127) + 1, hf = tid >> 7;
    const int hp = (tid < 32) ? 0 : 129;
    const uint32_t* wslot = &s_w[(g * 4 + tg) * 12]; // tap t adds t*384 words

    for (;;) {
        if (tid == 0) s_tile = atomicAdd(&g_tile_ctr, 1u);
        __syncthreads();
        const unsigned t5 = s_tile;
        if (t5 >= NTILES) break;
        const int w0 = (int)(t5 & 3) * 128;
        const int h0 = (int)((t5 >> 2) & 127) * ROWS;
        const int n  = (int)(t5 >> 9);
        const float* xn = x + (size_t)n * Cc * HW;

        const float* pmain = xn + (size_t)(hf * 16) * HW + (w0 + (tid & 127));
        const int wh  = w0 - 1 + hp;
        const bool whv = (wh >= 0) && (wh < Ww);

        load_row_full(s_a + 0 * RSTRIDE, xn, h0 - 1, w0, inv);
        load_row_full(s_a + 1 * RSTRIDE, xn, h0,     w0, inv);
        load_row_full(s_a + 2 * RSTRIDE, xn, h0 + 1, w0, inv);
        __syncthreads();

        #pragma unroll 1
        for (int i = 0; i < ROWS; i++) {
            // ---- phase A: issue fp32 loads for input row h0+i+2 ------------
            float f[16];
            float fhalo = 0.f;
            const int rp = h0 + i + 2;
            const bool pf = (i <= ROWS - 2);
            const bool vr = pf && (rp < Hh);
            #pragma unroll
            for (int k = 0; k < 16; k++)
                f[k] = vr ? __ldg(pmain + (size_t)rp * Ww + (size_t)k * HW) : 0.f;
            if (tid < 64 && vr && whv)
                fhalo = __ldg(xn + (size_t)(tid & 31) * HW + (size_t)rp * Ww + wh);

            // ---- phase B: dual-pipe compute of output row h0+i -------------
            const int h = h0 + i;
            int acc[2][4];                 // tensor accumulators (oc 0-15)
            acc[0][0] = 0; acc[0][1] = 0; acc[0][2] = 0; acc[0][3] = 0;
            acc[1][0] = 0; acc[1][1] = 0; acc[1][2] = 0; acc[1][3] = 0;
            int accd[8];                   // dp4a accumulators (8 oc, own px)
            #pragma unroll
            for (int o = 0; o < 8; o++) accd[o] = 0;

            #pragma unroll
            for (int t = 0; t < 9; t++) {
                const int dh = t / 3, dw = t % 3;
                const char* buf = s_a + ((i + dh) & 3) * RSTRIDE;
                // tensor A fragments (4B each, swizzle-aware)
                {
                    const int pxa = warp * 16 + g + dw;       // px for rows g
                    const int pxb = pxa + 8;                  // px for rows g+8
                    uint32_t a0 = *(const uint32_t*)(buf + ring_off(pxa, 0) + tg * 4);
                    uint32_t a2 = *(const uint32_t*)(buf + ring_off(pxa, 1) + tg * 4);
                    uint32_t a1 = *(const uint32_t*)(buf + ring_off(pxb, 0) + tg * 4);
                    uint32_t a3 = *(const uint32_t*)(buf + ring_off(pxb, 1) + tg * 4);
                    const uint32_t* wt = wslot + t * 384;
                    uint2 b0 = *(const uint2*)(wt);        // nt0,nt1 khalf0
                    uint2 b1 = *(const uint2*)(wt + 4);    // nt0,nt1 khalf1
                    mma_s8(acc[0], a0, a1, a2, a3, b0.x, b1.x);
                    mma_s8(acc[1], a0, a1, a2, a3, b0.y, b1.y);
                }
                // dp4a: this lane's pixel, 8 oc
                {
                    const int pxd = warp * 16 + dpx + dw;
                    uint4 A0 = *(const uint4*)(buf + ring_off(pxd, 0));
                    uint4 A1 = *(const uint4*)(buf + ring_off(pxd, 1));
                    const uint32_t* wb = &s_w2[och * 72 + t * 8];
                    #pragma unroll
                    for (int o = 0; o < 8; o++) {
                        uint4 W0 = *(const uint4*)(wb + o * 72);
                        uint4 W1 = *(const uint4*)(wb + o * 72 + 4);
                        int s = accd[o];
                        s = __dp4a((int)A0.x, (int)W0.x, s);
                        s = __dp4a((int)A0.y, (int)W0.y, s);
                        s = __dp4a((int)A0.z, (int)W0.z, s);
                        s = __dp4a((int)A0.w, (int)W0.w, s);
                        s = __dp4a((int)A1.x, (int)W1.x, s);
                        s = __dp4a((int)A1.y, (int)W1.y, s);
                        s = __dp4a((int)A1.z, (int)W1.z, s);
                        s = __dp4a((int)A1.w, (int)W1.w, s);
                        accd[o] = s;
                    }
                }
            }
            // epilogue: tensor (oc 0-15, C m16n8 layout) + dp4a (oc 16-31)
            {
                float* ob = out + (size_t)n * OC * HW + (size_t)h * Ww
                          + (w0 + warp * 16);
                #pragma unroll
                for (int nt = 0; nt < 2; nt++) {
                    int oc0 = nt * 8 + tg * 2;
                    float* p0 = ob + (size_t)oc0 * HW;
                    float* p1 = p0 + HW;
                    p0[g]     = (float)acc[nt][0] * sc + bv[2 * nt];
                    p1[g]     = (float)acc[nt][1] * sc + bv[2 * nt + 1];
                    p0[g + 8] = (float)acc[nt][2] * sc + bv[2 * nt];
                    p1[g + 8] = (float)acc[nt][3] * sc + bv[2 * nt + 1];
                }
                float* od = ob + (size_t)(16 + och) * HW + dpx;
                #pragma unroll
                for (int o = 0; o < 8; o++)
                    od[(size_t)o * HW] = (float)accd[o] * sc + bd[o];
            }

            // ---- phase D: quantize + store row rp into buf (i+3)&3 ---------
            if (pf) {
                char* dst = s_a + ((i + 3) & 3) * RSTRIDE;
                uint32_t wd[4];
                #pragma unroll
                for (int q4 = 0; q4 < 4; q4++) {
                    uint32_t pw = 0;
                    #pragma unroll
                    for (int b = 0; b < 4; b++) {
                        int q = max(-127, min(127, __float2int_rn(f[q4 * 4 + b] * inv)));
                        pw |= (uint32_t)(q & 0xFF) << (8 * b);
                    }
                    wd[q4] = pw;
                }
                *(uint4*)(dst + ring_off(pxm, hf)) =
                    make_uint4(wd[0], wd[1], wd[2], wd[3]);
                if (tid < 64) {
                    int q = max(-127, min(127, __float2int_rn(fhalo * inv)));
                    *(int8_t*)(dst + ring_off(hp, (tid & 31) >> 4) + (tid & 15)) =
                        (int8_t)q;
                }
            }
            __syncthreads();
        }
    }
}

// ---------------- launch ------------------------------------------------------
extern "C" void kernel_launch(void* const* d_in, const int* in_sizes, int n_in,
                              void* d_out, int out_size) {
    const float* x    = (const float*)d_in[0];
    const float* wgt  = (const float*)d_in[1];
    const float* bias = (const float*)d_in[2];
    float* out        = (float*)d_out;

    const int n4 = (Nn * Cc * HW) / 4; // 16,777,216 float4
    k_absmax<<<2048, 256>>>((const float4*)x, wgt, n4);

    k_conv<<<NCTA, 256>>>(x, out, bias);
}